// round 16
// baseline (speedup 1.0000x reference)
#include <cuda_runtime.h>
#include <cuda_bf16.h>
#include <stdint.h>
#include <math.h>
#include <float.h>

#define B_SZ     8
#define N_TOK    4096
#define DIM      512
#define HEADS    8
#define DH       64
#define M_LM     256
#define L_PER    16
#define E3       1536
#define BN       (B_SZ * N_TOK)         // 32768
#define BHN      (B_SZ * HEADS)         // 64
#define KER      33
#define KVSPLIT  8

typedef __nv_bfloat16 bf16;

// ---------------------------------------------------------------------------
// Device scratch
// ---------------------------------------------------------------------------
__device__ __align__(256) bf16 g_xn   [BN * DIM];
__device__ __align__(256) bf16 g_qkv  [BN * E3];
__device__ __align__(256) bf16 g_vc   [BHN * N_TOK * DH];
__device__ __align__(256) bf16 g_ql   [BHN * M_LM * DH];
__device__ __align__(256) bf16 g_kl   [BHN * M_LM * DH];
__device__ __align__(256) bf16 g_attn1[BHN * N_TOK * M_LM];
__device__ __align__(256) bf16 g_attn3[BHN * M_LM * N_TOK];
__device__ __align__(256) bf16 g_a2   [BHN * M_LM * M_LM];
__device__ __align__(256) bf16 g_z    [BHN * M_LM * M_LM];
__device__ __align__(256) bf16 g_z2   [BHN * M_LM * M_LM];
__device__ __align__(256) bf16 g_az   [BHN * M_LM * M_LM];
__device__ __align__(256) bf16 g_t1   [BHN * M_LM * M_LM];
__device__ __align__(256) bf16 g_t2   [BHN * M_LM * M_LM];
__device__ __align__(256) bf16 g_kv   [BHN * M_LM * DH];
__device__ __align__(256) bf16 g_zkv  [BHN * M_LM * DH];
__device__ __align__(256) float g_kvp [KVSPLIT * BHN * M_LM * DH];
__device__ __align__(256) bf16 g_y    [BN * DIM];
__device__ __align__(256) bf16 g_qkvw [E3 * DIM];
__device__ __align__(256) bf16 g_outw [DIM * DIM];
__device__ __align__(256) float g_scal[2];

// ---------------------------------------------------------------------------
// Helpers
// ---------------------------------------------------------------------------
__device__ __forceinline__ uint32_t packbf(float lo, float hi) {
    uint32_t r;
    asm("cvt.rn.bf16x2.f32 %0, %1, %2;" : "=r"(r) : "f"(hi), "f"(lo));
    return r;
}
__device__ __forceinline__ uint32_t smem_u32(const void* p) {
    return (uint32_t)__cvta_generic_to_shared(p);
}
__device__ __forceinline__ void cpasync16(uint32_t dst, const void* src) {
    asm volatile("cp.async.cg.shared.global [%0], [%1], 16;" :: "r"(dst), "l"(src));
}
__device__ __forceinline__ void ldmx4(uint32_t& r0, uint32_t& r1, uint32_t& r2,
                                      uint32_t& r3, uint32_t addr) {
    asm volatile("ldmatrix.sync.aligned.m8n8.x4.shared.b16 {%0,%1,%2,%3}, [%4];"
                 : "=r"(r0), "=r"(r1), "=r"(r2), "=r"(r3) : "r"(addr));
}
__device__ __forceinline__ void ldmx4t(uint32_t& r0, uint32_t& r1, uint32_t& r2,
                                       uint32_t& r3, uint32_t addr) {
    asm volatile("ldmatrix.sync.aligned.m8n8.x4.trans.shared.b16 {%0,%1,%2,%3}, [%4];"
                 : "=r"(r0), "=r"(r1), "=r"(r2), "=r"(r3) : "r"(addr));
}
__device__ __forceinline__ void mma16816(float* c, const uint32_t* a, const uint32_t* b) {
    asm volatile("mma.sync.aligned.m16n8k16.row.col.f32.bf16.bf16.f32 "
                 "{%0,%1,%2,%3}, {%4,%5,%6,%7}, {%8,%9}, {%0,%1,%2,%3};"
                 : "+f"(c[0]), "+f"(c[1]), "+f"(c[2]), "+f"(c[3])
                 : "r"(a[0]), "r"(a[1]), "r"(a[2]), "r"(a[3]), "r"(b[0]), "r"(b[1]));
}

__device__ __forceinline__ float bredSum(float v, float* sm) {
    #pragma unroll
    for (int o = 16; o; o >>= 1) v += __shfl_xor_sync(0xffffffffu, v, o);
    int w = threadIdx.x >> 5, l = threadIdx.x & 31;
    if (l == 0) sm[w] = v;
    __syncthreads();
    if (w == 0) {
        v = (l < 8) ? sm[l] : 0.0f;
        #pragma unroll
        for (int o = 4; o; o >>= 1) v += __shfl_xor_sync(0xffffffffu, v, o);
        if (l == 0) sm[0] = v;
    }
    __syncthreads();
    v = sm[0];
    __syncthreads();
    return v;
}
__device__ __forceinline__ float bredMax(float v, float* sm) {
    #pragma unroll
    for (int o = 16; o; o >>= 1) v = fmaxf(v, __shfl_xor_sync(0xffffffffu, v, o));
    int w = threadIdx.x >> 5, l = threadIdx.x & 31;
    if (l == 0) sm[w] = v;
    __syncthreads();
    if (w == 0) {
        v = (l < 8) ? sm[l] : -FLT_MAX;
        #pragma unroll
        for (int o = 4; o; o >>= 1) v = fmaxf(v, __shfl_xor_sync(0xffffffffu, v, o));
        if (l == 0) sm[0] = v;
    }
    __syncthreads();
    v = sm[0];
    __syncthreads();
    return v;
}

// ---------------------------------------------------------------------------
// BF16 GEMM: tile 128 x (4*WN) x 16, 4-stage cp.async pipeline + ldmatrix,
// wait_group 1 + B-fragment software pipelining (prefetch slot kt+1).
// MODE 0: bf16 C = diag*I + alpha*A.op(B)
// MODE 1: f32  C = acc + Xres*omega + Obias
// MODE 2: bf16 C = acc AND C2 = diag*I - acc
// MODE 3: f32  C = acc (split-K partial)
// ---------------------------------------------------------------------------
template <bool TRANSB, int WN, int MODE>
__global__ void __launch_bounds__(256, 2)
bgemm_kernel(const bf16* __restrict__ Amat, const bf16* __restrict__ Bmat,
             void* __restrict__ Cvoid, bf16* __restrict__ C2,
             const float* __restrict__ Xres, const float* __restrict__ Obias,
             const float* __restrict__ Omg,
             int K, int lda, int ldb, int ldc,
             long long sAo, long long sAi, long long sBo, long long sBi,
             long long sCo, long long sCi, int Hdiv, float alpha, float diag) {
    constexpr int BNT  = WN * 4;
    constexpr int NT   = WN / 8;
    constexpr int BUFA = 128 * 32;
    constexpr int BUFB = BNT * 32;

    __shared__ __align__(16) uint8_t smA[4 * BUFA];
    __shared__ __align__(16) uint8_t smB[4 * BUFB];

    int zb = blockIdx.z;
    int zo = zb / Hdiv, zi = zb - zo * Hdiv;
    Amat += zo * sAo + zi * sAi;
    Bmat += zo * sBo + zi * sBi;

    const int m0 = blockIdx.y * 128, n0 = blockIdx.x * BNT;
    const int tid = threadIdx.x, lane = tid & 31, warp = tid >> 5;
    const int wm = warp & 1, wn = warp >> 1;

    const int awr = tid >> 1, awh = tid & 1;
    const uint32_t awAddr = smem_u32(smA) + awr * 32 + ((awh ^ ((awr >> 2) & 1)) << 4);
    const bf16* agp = Amat + (long long)(m0 + awr) * lda + awh * 8;

    uint32_t bwAddr = 0;
    const bf16* bgp = nullptr;
    bool bact;
    long long bAdv;
    if (TRANSB) {
        bact = (BNT == 128) || (tid < 128);
        int bwr = (tid >> 1) & (BNT - 1);
        int bwh = tid & 1;
        bwAddr = smem_u32(smB) + bwr * 32 + ((bwh ^ ((bwr >> 2) & 1)) << 4);
        bgp = Bmat + (long long)(n0 + bwr) * ldb + bwh * 8;
        bAdv = 16;
    } else {
        constexpr int CH = BNT / 8;
        bact = tid < 16 * CH;
        int bk = (tid / CH) & 15, bc = tid % CH;
        bwAddr = smem_u32(smB) + bk * (BNT * 2) + (((bc ^ (bk & 7)) & (CH - 1)) << 4)
                 + ((bc & ~(CH - 1)) << 4);
        bgp = Bmat + (long long)bk * ldb + n0 + bc * 8;
        bAdv = (long long)16 * ldb;
    }

    const int rl = (lane & 7) + ((lane >> 3) & 1) * 8;
    const int lh = (lane >> 4) & 1;
    const int swz = lh ^ ((rl >> 2) & 1);
    const uint32_t aF = smem_u32(smA) + (wm * 64 + rl) * 32 + swz * 16;
    uint32_t bF[NT / 2];
    if (TRANSB) {
        #pragma unroll
        for (int p = 0; p < NT / 2; p++)
            bF[p] = smem_u32(smB) + (wn * WN + p * 16 + rl) * 32 + swz * 16;
    } else {
        const int kf = (lane & 7) + ((lane >> 4) & 1) * 8;
        const int cOff = (lane >> 3) & 1;
        #pragma unroll
        for (int p = 0; p < NT / 2; p++) {
            int ch = wn * NT + p * 2 + cOff;
            bF[p] = smem_u32(smB) + kf * (BNT * 2) + ((ch ^ (kf & 7)) << 4);
        }
    }

    float acc[4][NT][4] = {};
    const int ktiles = K >> 4;

    // ---- prologue: issue stages 0..2 ----
    #pragma unroll
    for (int s = 0; s < 3; s++) {
        if (s < ktiles) {
            cpasync16(awAddr + s * BUFA, agp);
            if (bact) cpasync16(bwAddr + s * BUFB, bgp);
            agp += 16;
            bgp += bAdv;
        }
        asm volatile("cp.async.commit_group;");
    }

    // pre-load B fragments of slot 0
    uint32_t bnext[NT][2];
    asm volatile("cp.async.wait_group 2;");
    __syncthreads();
    #pragma unroll
    for (int p = 0; p < NT / 2; p++) {
        uint32_t r0, r1, r2, r3;
        if (TRANSB) ldmx4 (r0, r1, r2, r3, bF[p]);
        else        ldmx4t(r0, r1, r2, r3, bF[p]);
        bnext[2 * p][0] = r0; bnext[2 * p + 1][0] = r1;
        bnext[2 * p][1] = r2; bnext[2 * p + 1][1] = r3;
    }

    for (int kt = 0; kt < ktiles; kt++) {
        asm volatile("cp.async.wait_group 1;");
        __syncthreads();
        const int slot = kt & 3;
        if (kt + 3 < ktiles) {
            int ws = (kt + 3) & 3;
            cpasync16(awAddr + ws * BUFA, agp);
            if (bact) cpasync16(bwAddr + ws * BUFB, bgp);
            agp += 16;
            bgp += bAdv;
        }
        asm volatile("cp.async.commit_group;");

        // current B fragments come from the prefetch
        uint32_t bfr[NT][2];
        #pragma unroll
        for (int nt = 0; nt < NT; nt++) {
            bfr[nt][0] = bnext[nt][0];
            bfr[nt][1] = bnext[nt][1];
        }

        // A fragments for this slot
        uint32_t a[4][4];
        #pragma unroll
        for (int mt = 0; mt < 4; mt++)
            ldmx4(a[mt][0], a[mt][1], a[mt][2], a[mt][3], aF + slot * BUFA + mt * 512);

        // prefetch B fragments for slot kt+1 (stage kt+1 is complete per wait_group 1)
        if (kt + 1 < ktiles) {
            int ns = (kt + 1) & 3;
            #pragma unroll
            for (int p = 0; p < NT / 2; p++) {
                uint32_t r0, r1, r2, r3;
                if (TRANSB) ldmx4 (r0, r1, r2, r3, bF[p] + ns * BUFB);
                else        ldmx4t(r0, r1, r2, r3, bF[p] + ns * BUFB);
                bnext[2 * p][0] = r0; bnext[2 * p + 1][0] = r1;
                bnext[2 * p][1] = r2; bnext[2 * p + 1][1] = r3;
            }
        }

        #pragma unroll
        for (int nt = 0; nt < NT; nt++)
            #pragma unroll
            for (int mt = 0; mt < 4; mt++)
                mma16816(&acc[mt][nt][0], &a[mt][0], &bfr[nt][0]);
    }

    const int g = lane >> 2, t4 = lane & 3;
    if (MODE == 1) {
        float* Cm = (float*)Cvoid + zo * sCo + zi * sCi;
        const float om = Omg[0];
        #pragma unroll
        for (int mt = 0; mt < 4; mt++) {
            int r0 = m0 + wm * 64 + mt * 16 + g;
            #pragma unroll
            for (int nt = 0; nt < NT; nt++) {
                int c0 = n0 + wn * WN + nt * 8 + t4 * 2;
                long long i0 = (long long)r0 * ldc + c0;
                long long i1 = (long long)(r0 + 8) * ldc + c0;
                float2 x0 = *(const float2*)(Xres + i0);
                float2 x1 = *(const float2*)(Xres + i1);
                float2 b0 = *(const float2*)(Obias + c0);
                float2 v0, v1;
                v0.x = acc[mt][nt][0] + x0.x * om + b0.x;
                v0.y = acc[mt][nt][1] + x0.y * om + b0.y;
                v1.x = acc[mt][nt][2] + x1.x * om + b0.x;
                v1.y = acc[mt][nt][3] + x1.y * om + b0.y;
                *(float2*)(Cm + i0) = v0;
                *(float2*)(Cm + i1) = v1;
            }
        }
    } else if (MODE == 2) {
        bf16* Cm = (bf16*)Cvoid + zo * sCo + zi * sCi;
        bf16* Dm = C2 + zo * sCo + zi * sCi;
        #pragma unroll
        for (int mt = 0; mt < 4; mt++) {
            int r0 = m0 + wm * 64 + mt * 16 + g;
            #pragma unroll
            for (int nt = 0; nt < NT; nt++) {
                int c0 = n0 + wn * WN + nt * 8 + t4 * 2;
                float e0 = acc[mt][nt][0], e1 = acc[mt][nt][1];
                float e2 = acc[mt][nt][2], e3 = acc[mt][nt][3];
                *(uint32_t*)(Cm + (long long)r0 * ldc + c0) = packbf(e0, e1);
                *(uint32_t*)(Cm + (long long)(r0 + 8) * ldc + c0) = packbf(e2, e3);
                float d0 = ((r0 == c0)     ? diag : 0.0f) - e0;
                float d1 = ((r0 == c0 + 1) ? diag : 0.0f) - e1;
                float d2 = ((r0 + 8 == c0)     ? diag : 0.0f) - e2;
                float d3 = ((r0 + 8 == c0 + 1) ? diag : 0.0f) - e3;
                *(uint32_t*)(Dm + (long long)r0 * ldc + c0) = packbf(d0, d1);
                *(uint32_t*)(Dm + (long long)(r0 + 8) * ldc + c0) = packbf(d2, d3);
            }
        }
    } else if (MODE == 3) {
        float* Cm = (float*)Cvoid + zo * sCo + zi * sCi;
        #pragma unroll
        for (int mt = 0; mt < 4; mt++) {
            int r0 = m0 + wm * 64 + mt * 16 + g;
            #pragma unroll
            for (int nt = 0; nt < NT; nt++) {
                int c0 = n0 + wn * WN + nt * 8 + t4 * 2;
                *(float2*)(Cm + (long long)r0 * ldc + c0) =
                    make_float2(acc[mt][nt][0], acc[mt][nt][1]);
                *(float2*)(Cm + (long long)(r0 + 8) * ldc + c0) =
                    make_float2(acc[mt][nt][2], acc[mt][nt][3]);
            }
        }
    } else {
        bf16* Cm = (bf16*)Cvoid + zo * sCo + zi * sCi;
        #pragma unroll
        for (int mt = 0; mt < 4; mt++) {
            int r0 = m0 + wm * 64 + mt * 16 + g;
            #pragma unroll
            for (int nt = 0; nt < NT; nt++) {
                int c0 = n0 + wn * WN + nt * 8 + t4 * 2;
                float e0 = alpha * acc[mt][nt][0] + ((r0 == c0)     ? diag : 0.0f);
                float e1 = alpha * acc[mt][nt][1] + ((r0 == c0 + 1) ? diag : 0.0f);
                float e2 = alpha * acc[mt][nt][2] + ((r0 + 8 == c0)     ? diag : 0.0f);
                float e3 = alpha * acc[mt][nt][3] + ((r0 + 8 == c0 + 1) ? diag : 0.0f);
                *(uint32_t*)(Cm + (long long)r0 * ldc + c0) = packbf(e0, e1);
                *(uint32_t*)(Cm + (long long)(r0 + 8) * ldc + c0) = packbf(e2, e3);
            }
        }
    }
}

static inline void launch_b128(bool transB, const bf16* A, const bf16* Bm, bf16* C,
                               int M, int N, int K, int lda, int ldb, int ldc,
                               long long sAo, long long sAi, long long sBo, long long sBi,
                               long long sCo, long long sCi, int Hdiv, int batch,
                               float alpha, float diag) {
    dim3 grid(N / 128, M / 128, batch), block(256);
    if (transB)
        bgemm_kernel<true, 32, 0><<<grid, block>>>(A, Bm, C, nullptr, nullptr, nullptr,
            nullptr, K, lda, ldb, ldc, sAo, sAi, sBo, sBi, sCo, sCi, Hdiv, alpha, diag);
    else
        bgemm_kernel<false, 32, 0><<<grid, block>>>(A, Bm, C, nullptr, nullptr, nullptr,
            nullptr, K, lda, ldb, ldc, sAo, sAi, sBo, sBi, sCo, sCi, Hdiv, alpha, diag);
}

static inline void launch_b64(bool transB, const bf16* A, const bf16* Bm, bf16* C,
                              int M, int N, int K, int lda, int ldb, int ldc,
                              long long sAo, long long sAi, long long sBo, long long sBi,
                              long long sCo, long long sCi, int Hdiv, int batch,
                              float alpha, float diag) {
    dim3 grid(N / 64, M / 128, batch), block(256);
    if (transB)
        bgemm_kernel<true, 16, 0><<<grid, block>>>(A, Bm, C, nullptr, nullptr, nullptr,
            nullptr, K, lda, ldb, ldc, sAo, sAi, sBo, sBi, sCo, sCi, Hdiv, alpha, diag);
    else
        bgemm_kernel<false, 16, 0><<<grid, block>>>(A, Bm, C, nullptr, nullptr, nullptr,
            nullptr, K, lda, ldb, ldc, sAo, sAi, sBo, sBi, sCo, sCi, Hdiv, alpha, diag);
}

// ---------------------------------------------------------------------------
// Fused GEMM + row softmax: P = softmax(alpha * A @ B^T), tile M=64 x N=256, K=64.
// ---------------------------------------------------------------------------
__global__ void __launch_bounds__(256)
attn_sm_kernel(const bf16* __restrict__ Amat, const bf16* __restrict__ Bmat,
               bf16* __restrict__ Cmat, int lda, int ldb,
               long long sAo, long long sAi, long long sBo, long long sBi,
               long long sCo, long long sCi, float alpha) {
    __shared__ __align__(16) uint8_t smA[8192];
    __shared__ __align__(16) uint8_t smB[32768];
    __shared__ float rred[64][8];

    int zb = blockIdx.z;
    int zo = zb >> 3, zi = zb & 7;
    Amat += zo * sAo + zi * sAi;
    Bmat += zo * sBo + zi * sBi;
    Cmat += zo * sCo + zi * sCi;

    const int m0 = blockIdx.y * 64;
    const int tid = threadIdx.x, lane = tid & 31, warp = tid >> 5;
    const int wm = warp & 1, wn = warp >> 1;

    #pragma unroll
    for (int it = 0; it < 2; it++) {
        int c = tid + it * 256;
        int row = c >> 3, q = c & 7;
        int ks = q >> 1, half = q & 1;
        uint32_t ad = smem_u32(smA) + ks * 2048 + row * 32 +
                      ((half ^ ((row >> 2) & 1)) << 4);
        cpasync16(ad, Amat + (long long)(m0 + row) * lda + q * 8);
    }
    #pragma unroll
    for (int it = 0; it < 8; it++) {
        int c = tid + it * 256;
        int row = c >> 3, q = c & 7;
        int ks = q >> 1, half = q & 1;
        uint32_t ad = smem_u32(smB) + ks * 8192 + row * 32 +
                      ((half ^ ((row >> 2) & 1)) << 4);
        cpasync16(ad, Bmat + (long long)row * ldb + q * 8);
    }
    asm volatile("cp.async.commit_group;");
    asm volatile("cp.async.wait_group 0;");
    __syncthreads();

    const int rl = (lane & 7) + ((lane >> 3) & 1) * 8;
    const int lh = (lane >> 4) & 1;
    const int swz = lh ^ ((rl >> 2) & 1);

    float acc[2][8][4] = {};
    #pragma unroll
    for (int ks = 0; ks < 4; ks++) {
        uint32_t a[2][4];
        #pragma unroll
        for (int mt = 0; mt < 2; mt++)
            ldmx4(a[mt][0], a[mt][1], a[mt][2], a[mt][3],
                  smem_u32(smA) + ks * 2048 + (wm * 32 + mt * 16 + rl) * 32 + swz * 16);
        uint32_t bfr[8][2];
        #pragma unroll
        for (int p = 0; p < 4; p++) {
            uint32_t r0, r1, r2, r3;
            ldmx4(r0, r1, r2, r3,
                  smem_u32(smB) + ks * 8192 + (wn * 64 + p * 16 + rl) * 32 + swz * 16);
            bfr[2 * p][0] = r0; bfr[2 * p + 1][0] = r1;
            bfr[2 * p][1] = r2; bfr[2 * p + 1][1] = r3;
        }
        #pragma unroll
        for (int nt = 0; nt < 8; nt++)
            #pragma unroll
            for (int mt = 0; mt < 2; mt++)
                mma16816(&acc[mt][nt][0], &a[mt][0], &bfr[nt][0]);
    }

    const int g = lane >> 2, t4 = lane & 3;
    #pragma unroll
    for (int mt = 0; mt < 2; mt++)
        #pragma unroll
        for (int nt = 0; nt < 8; nt++)
            #pragma unroll
            for (int c = 0; c < 4; c++) acc[mt][nt][c] *= alpha;

    #pragma unroll
    for (int mt = 0; mt < 2; mt++)
        #pragma unroll
        for (int hf = 0; hf < 2; hf++) {
            float m = -FLT_MAX;
            #pragma unroll
            for (int nt = 0; nt < 8; nt++)
                m = fmaxf(m, fmaxf(acc[mt][nt][hf * 2], acc[mt][nt][hf * 2 + 1]));
            m = fmaxf(m, __shfl_xor_sync(0xffffffffu, m, 1));
            m = fmaxf(m, __shfl_xor_sync(0xffffffffu, m, 2));
            if (t4 == 0) rred[wm * 32 + mt * 16 + hf * 8 + g][wn] = m;
        }
    __syncthreads();
    #pragma unroll
    for (int mt = 0; mt < 2; mt++)
        #pragma unroll
        for (int hf = 0; hf < 2; hf++) {
            int row = wm * 32 + mt * 16 + hf * 8 + g;
            float m = fmaxf(fmaxf(rred[row][0], rred[row][1]),
                            fmaxf(rred[row][2], rred[row][3]));
            float s = 0.f;
            #pragma unroll
            for (int nt = 0; nt < 8; nt++) {
                acc[mt][nt][hf * 2]     = expf(acc[mt][nt][hf * 2] - m);
                acc[mt][nt][hf * 2 + 1] = expf(acc[mt][nt][hf * 2 + 1] - m);
                s += acc[mt][nt][hf * 2] + acc[mt][nt][hf * 2 + 1];
            }
            s += __shfl_xor_sync(0xffffffffu, s, 1);
            s += __shfl_xor_sync(0xffffffffu, s, 2);
            if (t4 == 0) rred[row][4 + wn] = s;
        }
    __syncthreads();
    #pragma unroll
    for (int mt = 0; mt < 2; mt++)
        #pragma unroll
        for (int hf = 0; hf < 2; hf++) {
            int row = wm * 32 + mt * 16 + hf * 8 + g;
            float inv = 1.0f / (rred[row][4] + rred[row][5] +
                                rred[row][6] + rred[row][7]);
            #pragma unroll
            for (int nt = 0; nt < 8; nt++) {
                int c0 = wn * 64 + nt * 8 + t4 * 2;
                *(uint32_t*)(Cmat + (long long)(m0 + row) * 256 + c0) =
                    packbf(acc[mt][nt][hf * 2] * inv, acc[mt][nt][hf * 2 + 1] * inv);
            }
        }
}

// ---------------------------------------------------------------------------
// Small kernels
// ---------------------------------------------------------------------------
__global__ void f2b_kernel(const float4* __restrict__ in, uint2* __restrict__ out, int n4) {
    int i = blockIdx.x * 256 + threadIdx.x;
    if (i < n4) {
        float4 v = in[i];
        out[i] = make_uint2(packbf(v.x, v.y), packbf(v.z, v.w));
    }
}

__global__ void ln_kernel(const float* __restrict__ x, const float* __restrict__ w,
                          const float* __restrict__ bias, bf16* __restrict__ o) {
    __shared__ float sm[32];
    long long row = blockIdx.x;
    const float2* xr = (const float2*)(x + row * DIM);
    int t = threadIdx.x;
    float2 v = xr[t];
    float mu = bredSum(v.x + v.y, sm) * (1.0f / DIM);
    float d0 = v.x - mu, d1 = v.y - mu;
    float var = bredSum(d0 * d0 + d1 * d1, sm) * (1.0f / DIM);
    float rs = rsqrtf(var + 1e-5f);
    float2 wv = ((const float2*)w)[t];
    float2 bv = ((const float2*)bias)[t];
    ((uint32_t*)(o + row * DIM))[t] = packbf(d0 * rs * wv.x + bv.x, d1 * rs * wv.y + bv.y);
}

__global__ void vcopy_kernel(const bf16* __restrict__ qkv, bf16* __restrict__ vc) {
    long long idx = ((long long)blockIdx.x * 256 + threadIdx.x) * 8;
    long long d  = idx & 63;
    long long n  = (idx >> 6) & (N_TOK - 1);
    long long bh = idx >> 18;
    long long b = bh >> 3, h = bh & 7;
    uint4 v = *(const uint4*)(qkv + (b * N_TOK + n) * E3 + 2 * DIM + h * DH + d);
    *(uint4*)(vc + idx) = v;
}

__global__ void landmark_kernel(const bf16* __restrict__ qkv,
                                bf16* __restrict__ ql, bf16* __restrict__ kl) {
    int idx = blockIdx.x * 256 + threadIdx.x;
    int d  = idx & 63;
    int mi = (idx >> 6) & 255;
    int bh = idx >> 14;
    int bb = bh >> 3, h = bh & 7;
    const bf16* base = qkv + ((long long)(bb * N_TOK + mi * L_PER)) * E3 + h * DH + d;
    float sq = 0.f, sk = 0.f;
    #pragma unroll
    for (int j = 0; j < L_PER; j++) {
        sq += __bfloat162float(base[(long long)j * E3]);
        sk += __bfloat162float(base[(long long)j * E3 + DIM]);
    }
    ql[idx] = __float2bfloat16(sq * (0.125f / 16.0f));
    kl[idx] = __float2bfloat16(sk * (1.0f / 16.0f));
}

__global__ void softmax4096_kernel(bf16* __restrict__ data) {
    __shared__ float sm[32];
    uint32_t* p = (uint32_t*)(data + (long long)blockIdx.x * N_TOK);
    int t = threadIdx.x;
    float2 v[8];
    #pragma unroll
    for (int j = 0; j < 8; j++) {
        uint32_t wv = p[t + j * 256];
        v[j] = __bfloat1622float2(*(__nv_bfloat162*)&wv);
    }
    float mx = -FLT_MAX;
    #pragma unroll
    for (int j = 0; j < 8; j++) mx = fmaxf(mx, fmaxf(v[j].x, v[j].y));
    mx = bredMax(mx, sm);
    float s = 0.f;
    #pragma unroll
    for (int j = 0; j < 8; j++) {
        v[j].x = expf(v[j].x - mx); v[j].y = expf(v[j].y - mx);
        s += v[j].x + v[j].y;
    }
    s = bredSum(s, sm);
    float inv = 1.0f / s;
    #pragma unroll
    for (int j = 0; j < 8; j++)
        p[t + j * 256] = packbf(v[j].x * inv, v[j].y * inv);
}

__global__ void reset_kernel(float* scal) {
    if (threadIdx.x < 2) scal[threadIdx.x] = 0.0f;
}

__global__ void pinv_reduce_kernel(const bf16* __restrict__ a2, float* __restrict__ scal) {
    int bh = blockIdx.x, j = threadIdx.x;
    const bf16* a = a2 + (long long)bh * (M_LM * M_LM);
    float cs = 0.f, rs = 0.f;
    for (int i = 0; i < M_LM; i++) {
        cs += fabsf(__bfloat162float(a[i * M_LM + j]));
        rs += fabsf(__bfloat162float(a[j * M_LM + i]));
    }
    atomicMax((int*)&scal[0], __float_as_int(rs));
    atomicMax((int*)&scal[1], __float_as_int(cs));
}

__global__ void zinit_kernel(const bf16* __restrict__ a2, bf16* __restrict__ z,
                             const float* __restrict__ scal) {
    float inv = 1.0f / (scal[0] * scal[1]);
    int idx = blockIdx.x * 256 + threadIdx.x;
    int bh = idx >> 16, r = (idx >> 8) & 255, c = idx & 255;
    z[idx] = __float2bfloat16(
        __bfloat162float(a2[((long long)bh << 16) + (c << 8) + r]) * inv);
}

__global__ void kvred_kernel(const float* __restrict__ kvp, bf16* __restrict__ kv) {
    int idx = blockIdx.x * 256 + threadIdx.x;
    float s = 0.f;
    #pragma unroll
    for (int sp = 0; sp < KVSPLIT; sp++)
        s += kvp[(long long)sp * (BHN * M_LM * DH) + idx];
    kv[idx] = __float2bfloat16(s);
}

#define CONV_TI 128
__global__ void __launch_bounds__(256)
conv_add_kernel(const bf16* __restrict__ vc, const float* __restrict__ cw,
                bf16* __restrict__ Y) {
    __shared__ float w[KER];
    __shared__ __align__(16) bf16 vs[(CONV_TI + 32) * 64];
    int bh = blockIdx.y;
    int bb = bh >> 3, h = bh & 7;
    int i0 = blockIdx.x * CONV_TI;
    int tid = threadIdx.x;
    if (tid < KER) w[tid] = cw[h * KER + tid];

    const bf16* vbase = vc + (long long)bh * N_TOK * DH;
    #pragma unroll
    for (int c = 0; c < 5; c++) {
        int chunk = tid + c * 256;
        int row = chunk >> 3, ch = chunk & 7;
        int r = i0 - 16 + row;
        uint4 val = make_uint4(0, 0, 0, 0);
        if (r >= 0 && r < N_TOK)
            val = *(const uint4*)(vbase + (long long)r * DH + ch * 8);
        *(uint4*)(&vs[row * 64 + ch * 8]) = val;
    }
    __syncthreads();

    int j = tid & 63, iy = tid >> 6;
    #pragma unroll
    for (int s = 0; s < CONV_TI / 4; s++) {
        int ii = iy + s * 4;
        float acc = 0.f;
        #pragma unroll
        for (int t = 0; t < KER; t++)
            acc += w[t] * __bfloat162float(vs[(ii + t) * 64 + j]);
        long long o = ((long long)(bb * N_TOK + i0 + ii)) * DIM + h * DH + j;
        Y[o] = __float2bfloat16(__bfloat162float(Y[o]) + acc);
    }
}

// ---------------------------------------------------------------------------
// Launcher
// ---------------------------------------------------------------------------
template <typename T, size_t N>
static T* symp(T (&s)[N]) {
    void* p = nullptr;
    cudaGetSymbolAddress(&p, s);
    return (T*)p;
}

extern "C" void kernel_launch(void* const* d_in, const int* in_sizes, int n_in,
                              void* d_out, int out_size) {
    const float* x      = (const float*)d_in[0];
    const float* ln_w   = (const float*)d_in[1];
    const float* ln_b   = (const float*)d_in[2];
    const float* qkv_w  = (const float*)d_in[3];
    const float* out_w  = (const float*)d_in[4];
    const float* out_b  = (const float*)d_in[5];
    const float* conv_w = (const float*)d_in[6];
    const float* omega  = (const float*)d_in[7];
    float* out = (float*)d_out;

    bf16* xn    = symp(g_xn);
    bf16* qkv   = symp(g_qkv);
    bf16* vc    = symp(g_vc);
    bf16* ql    = symp(g_ql);
    bf16* kl    = symp(g_kl);
    bf16* attn1 = symp(g_attn1);
    bf16* attn3 = symp(g_attn3);
    bf16* a2    = symp(g_a2);
    bf16* z     = symp(g_z);
    bf16* z2    = symp(g_z2);
    bf16* az    = symp(g_az);
    bf16* t1    = symp(g_t1);
    bf16* t2    = symp(g_t2);
    bf16* kv    = symp(g_kv);
    bf16* zkv   = symp(g_zkv);
    float* kvp  = symp(g_kvp);
    bf16* Y     = symp(g_y);
    bf16* qkvwb = symp(g_qkvw);
    bf16* outwb = symp(g_outw);
    float* scal = symp(g_scal);

    const long long sA1 = (long long)N_TOK * M_LM;
    const long long sLM = (long long)M_LM * DH;
    const long long sMM = (long long)M_LM * M_LM;
    const long long sQB = (long long)N_TOK * E3;

    // 0. Weight conversion
    f2b_kernel<<<(E3 * DIM / 4 + 255) / 256, 256>>>((const float4*)qkv_w, (uint2*)qkvwb,
                                                    E3 * DIM / 4);
    f2b_kernel<<<(DIM * DIM / 4 + 255) / 256, 256>>>((const float4*)out_w, (uint2*)outwb,
                                                     DIM * DIM / 4);

    // 1. LayerNorm
    ln_kernel<<<BN, 256>>>(x, ln_w, ln_b, xn);

    // 2. QKV projection
    launch_b128(true, xn, qkvwb, qkv, BN, E3, DIM, DIM, DIM, E3,
                0, 0, 0, 0, 0, 0, 1, 1, 1.0f, 0.0f);

    // 2b. v contiguous copy
    vcopy_kernel<<<(BHN * N_TOK * DH / 8) / 256, 256>>>(qkv, vc);

    // 3. Landmark means
    landmark_kernel<<<(BHN * M_LM * DH) / 256, 256>>>(qkv, ql, kl);

    // 4. attn1 = softmax(scale * q @ kl^T)
    {
        dim3 grid(1, N_TOK / 64, BHN);
        attn_sm_kernel<<<grid, 256>>>(qkv, kl, attn1, E3, DH,
            sQB, DH, 8 * sLM, sLM, 8 * sA1, sA1, 0.125f);
    }

    // 5. a2 = softmax(ql @ kl^T)
    {
        dim3 grid(1, M_LM / 64, BHN);
        attn_sm_kernel<<<grid, 256>>>(ql, kl, a2, DH, DH,
            8 * sLM, sLM, 8 * sLM, sLM, 8 * sMM, sMM, 1.0f);
    }

    // 6. sim3 -> softmax -> attn3
    launch_b128(true, ql, qkv + DIM, attn3, M_LM, N_TOK, DH, DH, E3, N_TOK,
                8 * sLM, sLM, sQB, DH, 8 * sA1, sA1, HEADS, BHN, 1.0f, 0.0f);
    softmax4096_kernel<<<BHN * M_LM, 256>>>(attn3);

    // 7. pinv (6 Newton-Schulz iterations)
    reset_kernel<<<1, 32>>>(scal);
    pinv_reduce_kernel<<<BHN, 256>>>(a2, scal);
    zinit_kernel<<<(BHN * (int)sMM) / 256, 256>>>(a2, z, scal);

    bf16* zc = z;
    bf16* zn = z2;
    for (int it = 0; it < 6; it++) {
        {
            dim3 grid(M_LM / 128, M_LM / 128, BHN), block(256);
            bgemm_kernel<false, 32, 2><<<grid, block>>>(a2, zc, (void*)az, t1,
                nullptr, nullptr, nullptr, M_LM, M_LM, M_LM, M_LM,
                sMM, 0, sMM, 0, sMM, 0, 1, 1.0f, 7.0f);
        }
        launch_b128(false, az, t1, t2, M_LM, M_LM, M_LM, M_LM, M_LM, M_LM,
                    sMM, 0, sMM, 0, sMM, 0, 1, BHN, -1.0f, 15.0f);
        launch_b128(false, az, t2, t1, M_LM, M_LM, M_LM, M_LM, M_LM, M_LM,
                    sMM, 0, sMM, 0, sMM, 0, 1, BHN, -1.0f, 13.0f);
        launch_b128(false, zc, t1, zn, M_LM, M_LM, M_LM, M_LM, M_LM, M_LM,
                    sMM, 0, sMM, 0, sMM, 0, 1, BHN, 0.25f, 0.0f);
        bf16* tmp = zc; zc = zn; zn = tmp;
    }

    // 8. kv = attn3 @ v  (split-K x8)
    {
        dim3 grid(1, M_LM / 128, KVSPLIT * BHN), block(256);
        bgemm_kernel<false, 16, 3><<<grid, block>>>(attn3, vc, (void*)kvp, nullptr,
            nullptr, nullptr, nullptr, N_TOK / KVSPLIT, N_TOK, DH, DH,
            N_TOK / KVSPLIT, sA1,
            (long long)(N_TOK / KVSPLIT) * DH, (long long)N_TOK * DH,
            (long long)BHN * M_LM * DH, (long long)M_LM * DH,
            BHN, 1.0f, 0.0f);
        kvred_kernel<<<(BHN * M_LM * DH) / 256, 256>>>(kvp, kv);
    }

    // 9. zkv = attn2_inv @ kv
    launch_b64(false, zc, kv, zkv, M_LM, DH, M_LM, M_LM, DH, DH,
               sMM, 0, sLM, 0, sLM, 0, 1, BHN, 1.0f, 0.0f);

    // 10. Y = attn1 @ zkv
    launch_b64(false, attn1, zkv, Y, N_TOK, DH, M_LM, M_LM, DH, DIM,
               8 * sA1, sA1, 8 * sLM, sLM, (long long)N_TOK * DIM, DH,
               HEADS, BHN, 1.0f, 0.0f);

    // 11. conv residual
    conv_add_kernel<<<dim3(N_TOK / CONV_TI, BHN), 256>>>(vc, conv_w, Y);

    // 12. out projection with fused admin residual
    {
        dim3 grid(DIM / 128, BN / 128, 1), block(256);
        bgemm_kernel<true, 32, 1><<<grid, block>>>(Y, outwb, (void*)out, nullptr,
            x, out_b, omega, DIM, DIM, DIM, DIM, 0, 0, 0, 0, 0, 0, 1, 1.0f, 0.0f);
    }
}

// round 17
// speedup vs baseline: 1.1331x; 1.1331x over previous
#include <cuda_runtime.h>
#include <cuda_bf16.h>
#include <stdint.h>
#include <math.h>
#include <float.h>

#define B_SZ     8
#define N_TOK    4096
#define DIM      512
#define HEADS    8
#define DH       64
#define M_LM     256
#define L_PER    16
#define E3       1536
#define BN       (B_SZ * N_TOK)         // 32768
#define BHN      (B_SZ * HEADS)         // 64
#define KER      33

typedef __nv_bfloat16 bf16;

// ---------------------------------------------------------------------------
// Device scratch
// ---------------------------------------------------------------------------
__device__ __align__(256) bf16 g_xn   [BN * DIM];
__device__ __align__(256) bf16 g_qkv  [BN * E3];
__device__ __align__(256) bf16 g_vc   [BHN * N_TOK * DH];
__device__ __align__(256) bf16 g_ql   [BHN * M_LM * DH];
__device__ __align__(256) bf16 g_kl   [BHN * M_LM * DH];
__device__ __align__(256) bf16 g_attn1[BHN * N_TOK * M_LM];
__device__ __align__(256) bf16 g_a2   [BHN * M_LM * M_LM];
__device__ __align__(256) bf16 g_z    [BHN * M_LM * M_LM];
__device__ __align__(256) bf16 g_z2   [BHN * M_LM * M_LM];
__device__ __align__(256) bf16 g_az   [BHN * M_LM * M_LM];
__device__ __align__(256) bf16 g_t1   [BHN * M_LM * M_LM];
__device__ __align__(256) bf16 g_t2   [BHN * M_LM * M_LM];
__device__ __align__(256) bf16 g_kv   [BHN * M_LM * DH];
__device__ __align__(256) bf16 g_zkv  [BHN * M_LM * DH];
__device__ __align__(256) bf16 g_y    [BN * DIM];
__device__ __align__(256) bf16 g_qkvw [E3 * DIM];
__device__ __align__(256) bf16 g_outw [DIM * DIM];
__device__ __align__(256) float g_scal[2];

// ---------------------------------------------------------------------------
// Helpers
// ---------------------------------------------------------------------------
__device__ __forceinline__ uint32_t packbf(float lo, float hi) {
    uint32_t r;
    asm("cvt.rn.bf16x2.f32 %0, %1, %2;" : "=r"(r) : "f"(hi), "f"(lo));
    return r;
}
__device__ __forceinline__ uint32_t smem_u32(const void* p) {
    return (uint32_t)__cvta_generic_to_shared(p);
}
__device__ __forceinline__ void cpasync16(uint32_t dst, const void* src) {
    asm volatile("cp.async.cg.shared.global [%0], [%1], 16;" :: "r"(dst), "l"(src));
}
__device__ __forceinline__ void ldmx4(uint32_t& r0, uint32_t& r1, uint32_t& r2,
                                      uint32_t& r3, uint32_t addr) {
    asm volatile("ldmatrix.sync.aligned.m8n8.x4.shared.b16 {%0,%1,%2,%3}, [%4];"
                 : "=r"(r0), "=r"(r1), "=r"(r2), "=r"(r3) : "r"(addr));
}
__device__ __forceinline__ void ldmx4t(uint32_t& r0, uint32_t& r1, uint32_t& r2,
                                       uint32_t& r3, uint32_t addr) {
    asm volatile("ldmatrix.sync.aligned.m8n8.x4.trans.shared.b16 {%0,%1,%2,%3}, [%4];"
                 : "=r"(r0), "=r"(r1), "=r"(r2), "=r"(r3) : "r"(addr));
}
__device__ __forceinline__ void mma16816(float* c, const uint32_t* a, const uint32_t* b) {
    asm volatile("mma.sync.aligned.m16n8k16.row.col.f32.bf16.bf16.f32 "
                 "{%0,%1,%2,%3}, {%4,%5,%6,%7}, {%8,%9}, {%0,%1,%2,%3};"
                 : "+f"(c[0]), "+f"(c[1]), "+f"(c[2]), "+f"(c[3])
                 : "r"(a[0]), "r"(a[1]), "r"(a[2]), "r"(a[3]), "r"(b[0]), "r"(b[1]));
}

__device__ __forceinline__ float bredSum(float v, float* sm) {
    #pragma unroll
    for (int o = 16; o; o >>= 1) v += __shfl_xor_sync(0xffffffffu, v, o);
    int w = threadIdx.x >> 5, l = threadIdx.x & 31;
    if (l == 0) sm[w] = v;
    __syncthreads();
    if (w == 0) {
        v = (l < 8) ? sm[l] : 0.0f;
        #pragma unroll
        for (int o = 4; o; o >>= 1) v += __shfl_xor_sync(0xffffffffu, v, o);
        if (l == 0) sm[0] = v;
    }
    __syncthreads();
    v = sm[0];
    __syncthreads();
    return v;
}

// ---------------------------------------------------------------------------
// BF16 GEMM: tile 128 x (4*WN) x 16, 4-stage cp.async pipeline + ldmatrix.
// (exact R14 configuration — proven fastest)
// MODE 0: bf16 C = diag*I + alpha*A.op(B)
// MODE 1: f32  C = acc + Xres*omega + Obias
// MODE 2: bf16 C = acc AND C2 = diag*I - acc
// ---------------------------------------------------------------------------
template <bool TRANSB, int WN, int MODE>
__global__ void __launch_bounds__(256)
bgemm_kernel(const bf16* __restrict__ Amat, const bf16* __restrict__ Bmat,
             void* __restrict__ Cvoid, bf16* __restrict__ C2,
             const float* __restrict__ Xres, const float* __restrict__ Obias,
             const float* __restrict__ Omg,
             int K, int lda, int ldb, int ldc,
             long long sAo, long long sAi, long long sBo, long long sBi,
             long long sCo, long long sCi, int Hdiv, float alpha, float diag) {
    constexpr int BNT  = WN * 4;
    constexpr int NT   = WN / 8;
    constexpr int BUFA = 128 * 32;
    constexpr int BUFB = BNT * 32;

    __shared__ __align__(16) uint8_t smA[4 * BUFA];
    __shared__ __align__(16) uint8_t smB[4 * BUFB];

    int zb = blockIdx.z;
    int zo = zb / Hdiv, zi = zb - zo * Hdiv;
    Amat += zo * sAo + zi * sAi;
    Bmat += zo * sBo + zi * sBi;

    const int m0 = blockIdx.y * 128, n0 = blockIdx.x * BNT;
    const int tid = threadIdx.x, lane = tid & 31, warp = tid >> 5;
    const int wm = warp & 1, wn = warp >> 1;

    const int awr = tid >> 1, awh = tid & 1;
    const uint32_t awAddr = smem_u32(smA) + awr * 32 + ((awh ^ ((awr >> 2) & 1)) << 4);
    const bf16* agp = Amat + (long long)(m0 + awr) * lda + awh * 8;

    uint32_t bwAddr = 0;
    const bf16* bgp = nullptr;
    bool bact;
    long long bAdv;
    if (TRANSB) {
        bact = (BNT == 128) || (tid < 128);
        int bwr = (tid >> 1) & (BNT - 1);
        int bwh = tid & 1;
        bwAddr = smem_u32(smB) + bwr * 32 + ((bwh ^ ((bwr >> 2) & 1)) << 4);
        bgp = Bmat + (long long)(n0 + bwr) * ldb + bwh * 8;
        bAdv = 16;
    } else {
        constexpr int CH = BNT / 8;
        bact = tid < 16 * CH;
        int bk = (tid / CH) & 15, bc = tid % CH;
        bwAddr = smem_u32(smB) + bk * (BNT * 2) + (((bc ^ (bk & 7)) & (CH - 1)) << 4)
                 + ((bc & ~(CH - 1)) << 4);
        bgp = Bmat + (long long)bk * ldb + n0 + bc * 8;
        bAdv = (long long)16 * ldb;
    }

    const int rl = (lane & 7) + ((lane >> 3) & 1) * 8;
    const int lh = (lane >> 4) & 1;
    const int swz = lh ^ ((rl >> 2) & 1);
    const uint32_t aF = smem_u32(smA) + (wm * 64 + rl) * 32 + swz * 16;
    uint32_t bF[NT / 2];
    if (TRANSB) {
        #pragma unroll
        for (int p = 0; p < NT / 2; p++)
            bF[p] = smem_u32(smB) + (wn * WN + p * 16 + rl) * 32 + swz * 16;
    } else {
        const int kf = (lane & 7) + ((lane >> 4) & 1) * 8;
        const int cOff = (lane >> 3) & 1;
        #pragma unroll
        for (int p = 0; p < NT / 2; p++) {
            int ch = wn * NT + p * 2 + cOff;
            bF[p] = smem_u32(smB) + kf * (BNT * 2) + ((ch ^ (kf & 7)) << 4);
        }
    }

    float acc[4][NT][4] = {};
    const int ktiles = K >> 4;

    #pragma unroll
    for (int s = 0; s < 3; s++) {
        if (s < ktiles) {
            cpasync16(awAddr + s * BUFA, agp);
            if (bact) cpasync16(bwAddr + s * BUFB, bgp);
            agp += 16;
            bgp += bAdv;
        }
        asm volatile("cp.async.commit_group;");
    }

    for (int kt = 0; kt < ktiles; kt++) {
        asm volatile("cp.async.wait_group 2;");
        __syncthreads();
        const int slot = kt & 3;
        if (kt + 3 < ktiles) {
            int ws = (kt + 3) & 3;
            cpasync16(awAddr + ws * BUFA, agp);
            if (bact) cpasync16(bwAddr + ws * BUFB, bgp);
            agp += 16;
            bgp += bAdv;
        }
        asm volatile("cp.async.commit_group;");

        uint32_t a[4][4];
        #pragma unroll
        for (int mt = 0; mt < 4; mt++)
            ldmx4(a[mt][0], a[mt][1], a[mt][2], a[mt][3], aF + slot * BUFA + mt * 512);
        uint32_t bfr[NT][2];
        #pragma unroll
        for (int p = 0; p < NT / 2; p++) {
            uint32_t r0, r1, r2, r3;
            if (TRANSB) ldmx4 (r0, r1, r2, r3, bF[p] + slot * BUFB);
            else        ldmx4t(r0, r1, r2, r3, bF[p] + slot * BUFB);
            bfr[2 * p][0] = r0; bfr[2 * p + 1][0] = r1;
            bfr[2 * p][1] = r2; bfr[2 * p + 1][1] = r3;
        }
        #pragma unroll
        for (int nt = 0; nt < NT; nt++)
            #pragma unroll
            for (int mt = 0; mt < 4; mt++)
                mma16816(&acc[mt][nt][0], &a[mt][0], &bfr[nt][0]);
    }

    const int g = lane >> 2, t4 = lane & 3;
    if (MODE == 1) {
        float* Cm = (float*)Cvoid + zo * sCo + zi * sCi;
        const float om = Omg[0];
        #pragma unroll
        for (int mt = 0; mt < 4; mt++) {
            int r0 = m0 + wm * 64 + mt * 16 + g;
            #pragma unroll
            for (int nt = 0; nt < NT; nt++) {
                int c0 = n0 + wn * WN + nt * 8 + t4 * 2;
                long long i0 = (long long)r0 * ldc + c0;
                long long i1 = (long long)(r0 + 8) * ldc + c0;
                float2 x0 = *(const float2*)(Xres + i0);
                float2 x1 = *(const float2*)(Xres + i1);
                float2 b0 = *(const float2*)(Obias + c0);
                float2 v0, v1;
                v0.x = acc[mt][nt][0] + x0.x * om + b0.x;
                v0.y = acc[mt][nt][1] + x0.y * om + b0.y;
                v1.x = acc[mt][nt][2] + x1.x * om + b0.x;
                v1.y = acc[mt][nt][3] + x1.y * om + b0.y;
                *(float2*)(Cm + i0) = v0;
                *(float2*)(Cm + i1) = v1;
            }
        }
    } else if (MODE == 2) {
        bf16* Cm = (bf16*)Cvoid + zo * sCo + zi * sCi;
        bf16* Dm = C2 + zo * sCo + zi * sCi;
        #pragma unroll
        for (int mt = 0; mt < 4; mt++) {
            int r0 = m0 + wm * 64 + mt * 16 + g;
            #pragma unroll
            for (int nt = 0; nt < NT; nt++) {
                int c0 = n0 + wn * WN + nt * 8 + t4 * 2;
                float e0 = acc[mt][nt][0], e1 = acc[mt][nt][1];
                float e2 = acc[mt][nt][2], e3 = acc[mt][nt][3];
                *(uint32_t*)(Cm + (long long)r0 * ldc + c0) = packbf(e0, e1);
                *(uint32_t*)(Cm + (long long)(r0 + 8) * ldc + c0) = packbf(e2, e3);
                float d0 = ((r0 == c0)     ? diag : 0.0f) - e0;
                float d1 = ((r0 == c0 + 1) ? diag : 0.0f) - e1;
                float d2 = ((r0 + 8 == c0)     ? diag : 0.0f) - e2;
                float d3 = ((r0 + 8 == c0 + 1) ? diag : 0.0f) - e3;
                *(uint32_t*)(Dm + (long long)r0 * ldc + c0) = packbf(d0, d1);
                *(uint32_t*)(Dm + (long long)(r0 + 8) * ldc + c0) = packbf(d2, d3);
            }
        }
    } else {
        bf16* Cm = (bf16*)Cvoid + zo * sCo + zi * sCi;
        #pragma unroll
        for (int mt = 0; mt < 4; mt++) {
            int r0 = m0 + wm * 64 + mt * 16 + g;
            #pragma unroll
            for (int nt = 0; nt < NT; nt++) {
                int c0 = n0 + wn * WN + nt * 8 + t4 * 2;
                float e0 = alpha * acc[mt][nt][0] + ((r0 == c0)     ? diag : 0.0f);
                float e1 = alpha * acc[mt][nt][1] + ((r0 == c0 + 1) ? diag : 0.0f);
                float e2 = alpha * acc[mt][nt][2] + ((r0 + 8 == c0)     ? diag : 0.0f);
                float e3 = alpha * acc[mt][nt][3] + ((r0 + 8 == c0 + 1) ? diag : 0.0f);
                *(uint32_t*)(Cm + (long long)r0 * ldc + c0) = packbf(e0, e1);
                *(uint32_t*)(Cm + (long long)(r0 + 8) * ldc + c0) = packbf(e2, e3);
            }
        }
    }
}

static inline void launch_b128(bool transB, const bf16* A, const bf16* Bm, bf16* C,
                               int M, int N, int K, int lda, int ldb, int ldc,
                               long long sAo, long long sAi, long long sBo, long long sBi,
                               long long sCo, long long sCi, int Hdiv, int batch,
                               float alpha, float diag) {
    dim3 grid(N / 128, M / 128, batch), block(256);
    if (transB)
        bgemm_kernel<true, 32, 0><<<grid, block>>>(A, Bm, C, nullptr, nullptr, nullptr,
            nullptr, K, lda, ldb, ldc, sAo, sAi, sBo, sBi, sCo, sCi, Hdiv, alpha, diag);
    else
        bgemm_kernel<false, 32, 0><<<grid, block>>>(A, Bm, C, nullptr, nullptr, nullptr,
            nullptr, K, lda, ldb, ldc, sAo, sAi, sBo, sBi, sCo, sCi, Hdiv, alpha, diag);
}

static inline void launch_b64(bool transB, const bf16* A, const bf16* Bm, bf16* C,
                              int M, int N, int K, int lda, int ldb, int ldc,
                              long long sAo, long long sAi, long long sBo, long long sBi,
                              long long sCo, long long sCi, int Hdiv, int batch,
                              float alpha, float diag) {
    dim3 grid(N / 64, M / 128, batch), block(256);
    if (transB)
        bgemm_kernel<true, 16, 0><<<grid, block>>>(A, Bm, C, nullptr, nullptr, nullptr,
            nullptr, K, lda, ldb, ldc, sAo, sAi, sBo, sBi, sCo, sCi, Hdiv, alpha, diag);
    else
        bgemm_kernel<false, 16, 0><<<grid, block>>>(A, Bm, C, nullptr, nullptr, nullptr,
            nullptr, K, lda, ldb, ldc, sAo, sAi, sBo, sBi, sCo, sCi, Hdiv, alpha, diag);
}

// ---------------------------------------------------------------------------
// Flash-style fused kernel: kv[bh] = softmax_row(ql[bh] @ k[bh]^T) @ v[bh]
// CTA = (m-tile of 128 rows, bh). 8 warps, each owns 16 rows (softmax
// warp-local). K/V streamed in 64-row chunks, double-buffered cp.async.
// ---------------------------------------------------------------------------
__global__ void __launch_bounds__(256)
flash_kv_kernel(const bf16* __restrict__ qlm, const bf16* __restrict__ qkv,
                const bf16* __restrict__ vc, bf16* __restrict__ kvout) {
    __shared__ __align__(16) uint8_t smQ[16384];       // [4 ksub][128 rows][32B]
    __shared__ __align__(16) uint8_t smK[2][8192];     // [4 ksub][64 rows][32B]
    __shared__ __align__(16) uint8_t smV[2][8192];     // [4 kvsub][16 rows][128B]

    const int mt0 = blockIdx.x;            // 0..1
    const int bh  = blockIdx.y;            // 0..63
    const int bb  = bh >> 3, hh = bh & 7;
    const int m0  = mt0 * 128;

    const int tid = threadIdx.x, lane = tid & 31, warp = tid >> 5;
    const int g = lane >> 2, t4 = lane & 3;
    const int rl = (lane & 7) + ((lane >> 3) & 1) * 8;
    const int lh = (lane >> 4) & 1;
    const int swz = lh ^ ((rl >> 2) & 1);

    const bf16* kbase = qkv + (long long)bb * N_TOK * E3 + DIM + hh * DH;
    const bf16* vbase = vc + (long long)bh * N_TOK * DH;
    const bf16* qbase = qlm + (long long)bh * M_LM * DH;

    // ---- Q loads (once): 128 rows x 8 chunks of 16B ----
    #pragma unroll
    for (int it = 0; it < 4; it++) {
        int c = tid + it * 256;
        int row = c >> 3, qq = c & 7;
        int ks = qq >> 1, half = qq & 1;
        uint32_t ad = smem_u32(smQ) + ks * 4096 + row * 32 +
                      ((half ^ ((row >> 2) & 1)) << 4);
        cpasync16(ad, qbase + (long long)(m0 + row) * DH + qq * 8);
    }
    // ---- chunk 0 K/V loads ----
    {
        #pragma unroll
        for (int it = 0; it < 2; it++) {
            int c = tid + it * 256;
            int row = c >> 3, qq = c & 7;
            int ks = qq >> 1, half = qq & 1;
            uint32_t ad = smem_u32(smK[0]) + ks * 2048 + row * 32 +
                          ((half ^ ((row >> 2) & 1)) << 4);
            cpasync16(ad, kbase + (long long)row * E3 + qq * 8);
        }
        #pragma unroll
        for (int it = 0; it < 2; it++) {
            int c = tid + it * 256;
            int row = c >> 3, ch = c & 7;
            int sub = row >> 4, bkr = row & 15;
            uint32_t ad = smem_u32(smV[0]) + sub * 2048 + bkr * 128 +
                          ((ch ^ (bkr & 7)) << 4);
            cpasync16(ad, vbase + (long long)row * DH + ch * 8);
        }
    }
    asm volatile("cp.async.commit_group;");

    // V fragment lane addressing (k-major, CH=8)
    const int vkf = (lane & 7) + ((lane >> 4) & 1) * 8;
    const int vcOff = (lane >> 3) & 1;

    // Q fragments (loaded after first wait)
    uint32_t qf[4][4];
    bool qloaded = false;

    float m_run[2] = {-FLT_MAX, -FLT_MAX};
    float l_run[2] = {0.0f, 0.0f};
    float of[8][4] = {};

    const int NC = N_TOK / 64;             // 64 chunks
    for (int c = 0; c < NC; c++) {
        asm volatile("cp.async.wait_group 0;");
        __syncthreads();
        if (!qloaded) {
            #pragma unroll
            for (int ks = 0; ks < 4; ks++)
                ldmx4(qf[ks][0], qf[ks][1], qf[ks][2], qf[ks][3],
                      smem_u32(smQ) + ks * 4096 + (warp * 16 + rl) * 32 + swz * 16);
            qloaded = true;
        }
        // issue chunk c+1 into buffer (c+1)&1
        if (c + 1 < NC) {
            int nb = (c + 1) & 1;
            long long kv0 = (long long)(c + 1) * 64;
            #pragma unroll
            for (int it = 0; it < 2; it++) {
                int cc = tid + it * 256;
                int row = cc >> 3, qq = cc & 7;
                int ks = qq >> 1, half = qq & 1;
                uint32_t ad = smem_u32(smK[nb]) + ks * 2048 + row * 32 +
                              ((half ^ ((row >> 2) & 1)) << 4);
                cpasync16(ad, kbase + (kv0 + row) * E3 + qq * 8);
            }
            #pragma unroll
            for (int it = 0; it < 2; it++) {
                int cc = tid + it * 256;
                int row = cc >> 3, ch = cc & 7;
                int sub = row >> 4, bkr = row & 15;
                uint32_t ad = smem_u32(smV[nb]) + sub * 2048 + bkr * 128 +
                              ((ch ^ (bkr & 7)) << 4);
                cpasync16(ad, vbase + (kv0 + row) * DH + ch * 8);
            }
        }
        asm volatile("cp.async.commit_group;");

        const int buf = c & 1;
        // ---- S = q @ k^T  [16 x 64 per warp] ----
        float sacc[8][4] = {};
        #pragma unroll
        for (int ks = 0; ks < 4; ks++) {
            uint32_t bfr[8][2];
            #pragma unroll
            for (int p = 0; p < 4; p++) {
                uint32_t r0, r1, r2, r3;
                ldmx4(r0, r1, r2, r3,
                      smem_u32(smK[buf]) + ks * 2048 + (p * 16 + rl) * 32 + swz * 16);
                bfr[2 * p][0] = r0; bfr[2 * p + 1][0] = r1;
                bfr[2 * p][1] = r2; bfr[2 * p + 1][1] = r3;
            }
            #pragma unroll
            for (int nt = 0; nt < 8; nt++)
                mma16816(&sacc[nt][0], &qf[ks][0], &bfr[nt][0]);
        }

        // ---- online softmax (warp-local, rows g / g+8) ----
        #pragma unroll
        for (int hf = 0; hf < 2; hf++) {
            float cm = -FLT_MAX;
            #pragma unroll
            for (int nt = 0; nt < 8; nt++)
                cm = fmaxf(cm, fmaxf(sacc[nt][hf * 2], sacc[nt][hf * 2 + 1]));
            cm = fmaxf(cm, __shfl_xor_sync(0xffffffffu, cm, 1));
            cm = fmaxf(cm, __shfl_xor_sync(0xffffffffu, cm, 2));
            float Mn = fmaxf(m_run[hf], cm);
            float fac = expf(m_run[hf] - Mn);
            float s = 0.0f;
            #pragma unroll
            for (int nt = 0; nt < 8; nt++) {
                float e0 = expf(sacc[nt][hf * 2] - Mn);
                float e1 = expf(sacc[nt][hf * 2 + 1] - Mn);
                sacc[nt][hf * 2] = e0;
                sacc[nt][hf * 2 + 1] = e1;
                s += e0 + e1;
            }
            s += __shfl_xor_sync(0xffffffffu, s, 1);
            s += __shfl_xor_sync(0xffffffffu, s, 2);
            l_run[hf] = l_run[hf] * fac + s;
            m_run[hf] = Mn;
            #pragma unroll
            for (int nt = 0; nt < 8; nt++) {
                of[nt][hf * 2] *= fac;
                of[nt][hf * 2 + 1] *= fac;
            }
        }

        // ---- O += P @ V ----
        #pragma unroll
        for (int ks = 0; ks < 4; ks++) {
            uint32_t pa[4];
            pa[0] = packbf(sacc[2 * ks][0], sacc[2 * ks][1]);
            pa[1] = packbf(sacc[2 * ks][2], sacc[2 * ks][3]);
            pa[2] = packbf(sacc[2 * ks + 1][0], sacc[2 * ks + 1][1]);
            pa[3] = packbf(sacc[2 * ks + 1][2], sacc[2 * ks + 1][3]);
            #pragma unroll
            for (int p = 0; p < 4; p++) {
                int ch = p * 2 + vcOff;
                uint32_t r0, r1, r2, r3;
                ldmx4t(r0, r1, r2, r3,
                       smem_u32(smV[buf]) + ks * 2048 + vkf * 128 +
                       ((ch ^ (vkf & 7)) << 4));
                uint32_t b0[2] = {r0, r2};
                uint32_t b1[2] = {r1, r3};
                mma16816(&of[2 * p][0], pa, b0);
                mma16816(&of[2 * p + 1][0], pa, b1);
            }
        }
    }

    // ---- finalize: divide by l, store ----
    float inv0 = 1.0f / l_run[0];
    float inv1 = 1.0f / l_run[1];
    bf16* outp = kvout + (long long)bh * M_LM * DH;
    int r0 = m0 + warp * 16 + g;
    #pragma unroll
    for (int nt = 0; nt < 8; nt++) {
        int c0 = nt * 8 + t4 * 2;
        *(uint32_t*)(outp + (long long)r0 * DH + c0) =
            packbf(of[nt][0] * inv0, of[nt][1] * inv0);
        *(uint32_t*)(outp + (long long)(r0 + 8) * DH + c0) =
            packbf(of[nt][2] * inv1, of[nt][3] * inv1);
    }
}

// ---------------------------------------------------------------------------
// Fused GEMM + row softmax: P = softmax(alpha * A @ B^T), tile M=64 x N=256, K=64.
// ---------------------------------------------------------------------------
__global__ void __launch_bounds__(256)
attn_sm_kernel(const bf16* __restrict__ Amat, const bf16* __restrict__ Bmat,
               bf16* __restrict__ Cmat, int lda, int ldb,
               long long sAo, long long sAi, long long sBo, long long sBi,
               long long sCo, long long sCi, float alpha) {
    __shared__ __align__(16) uint8_t smA[8192];
    __shared__ __align__(16) uint8_t smB[32768];
    __shared__ float rred[64][8];

    int zb = blockIdx.z;
    int zo = zb >> 3, zi = zb & 7;
    Amat += zo * sAo + zi * sAi;
    Bmat += zo * sBo + zi * sBi;
    Cmat += zo * sCo + zi * sCi;

    const int m0 = blockIdx.y * 64;
    const int tid = threadIdx.x, lane = tid & 31, warp = tid >> 5;
    const int wm = warp & 1, wn = warp >> 1;

    #pragma unroll
    for (int it = 0; it < 2; it++) {
        int c = tid + it * 256;
        int row = c >> 3, q = c & 7;
        int ks = q >> 1, half = q & 1;
        uint32_t ad = smem_u32(smA) + ks * 2048 + row * 32 +
                      ((half ^ ((row >> 2) & 1)) << 4);
        cpasync16(ad, Amat + (long long)(m0 + row) * lda + q * 8);
    }
    #pragma unroll
    for (int it = 0; it < 8; it++) {
        int c = tid + it * 256;
        int row = c >> 3, q = c & 7;
        int ks = q >> 1, half = q & 1;
        uint32_t ad = smem_u32(smB) + ks * 8192 + row * 32 +
                      ((half ^ ((row >> 2) & 1)) << 4);
        cpasync16(ad, Bmat + (long long)row * ldb + q * 8);
    }
    asm volatile("cp.async.commit_group;");
    asm volatile("cp.async.wait_group 0;");
    __syncthreads();

    const int rl = (lane & 7) + ((lane >> 3) & 1) * 8;
    const int lh = (lane >> 4) & 1;
    const int swz = lh ^ ((rl >> 2) & 1);

    float acc[2][8][4] = {};
    #pragma unroll
    for (int ks = 0; ks < 4; ks++) {
        uint32_t a[2][4];
        #pragma unroll
        for (int mt = 0; mt < 2; mt++)
            ldmx4(a[mt][0], a[mt][1], a[mt][2], a[mt][3],
                  smem_u32(smA) + ks * 2048 + (wm * 32 + mt * 16 + rl) * 32 + swz * 16);
        uint32_t bfr[8][2];
        #pragma unroll
        for (int p = 0; p < 4; p++) {
            uint32_t r0, r1, r2, r3;
            ldmx4(r0, r1, r2, r3,
                  smem_u32(smB) + ks * 8192 + (wn * 64 + p * 16 + rl) * 32 + swz * 16);
            bfr[2 * p][0] = r0; bfr[2 * p + 1][0] = r1;
            bfr[2 * p][1] = r2; bfr[2 * p + 1][1] = r3;
        }
        #pragma unroll
        for (int nt = 0; nt < 8; nt++)
            #pragma unroll
            for (int mt = 0; mt < 2; mt++)
                mma16816(&acc[mt][nt][0], &a[mt][0], &bfr[nt][0]);
    }

    const int g = lane >> 2, t4 = lane & 3;
    #pragma unroll
    for (int mt = 0; mt < 2; mt++)
        #pragma unroll
        for (int nt = 0; nt < 8; nt++)
            #pragma unroll
            for (int c = 0; c < 4; c++) acc[mt][nt][c] *= alpha;

    #pragma unroll
    for (int mt = 0; mt < 2; mt++)
        #pragma unroll
        for (int hf = 0; hf < 2; hf++) {
            float m = -FLT_MAX;
            #pragma unroll
            for (int nt = 0; nt < 8; nt++)
                m = fmaxf(m, fmaxf(acc[mt][nt][hf * 2], acc[mt][nt][hf * 2 + 1]));
            m = fmaxf(m, __shfl_xor_sync(0xffffffffu, m, 1));
            m = fmaxf(m, __shfl_xor_sync(0xffffffffu, m, 2));
            if (t4 == 0) rred[wm * 32 + mt * 16 + hf * 8 + g][wn] = m;
        }
    __syncthreads();
    #pragma unroll
    for (int mt = 0; mt < 2; mt++)
        #pragma unroll
        for (int hf = 0; hf < 2; hf++) {
            int row = wm * 32 + mt * 16 + hf * 8 + g;
            float m = fmaxf(fmaxf(rred[row][0], rred[row][1]),
                            fmaxf(rred[row][2], rred[row][3]));
            float s = 0.f;
            #pragma unroll
            for (int nt = 0; nt < 8; nt++) {
                acc[mt][nt][hf * 2]     = expf(acc[mt][nt][hf * 2] - m);
                acc[mt][nt][hf * 2 + 1] = expf(acc[mt][nt][hf * 2 + 1] - m);
                s += acc[mt][nt][hf * 2] + acc[mt][nt][hf * 2 + 1];
            }
            s += __shfl_xor_sync(0xffffffffu, s, 1);
            s += __shfl_xor_sync(0xffffffffu, s, 2);
            if (t4 == 0) rred[row][4 + wn] = s;
        }
    __syncthreads();
    #pragma unroll
    for (int mt = 0; mt < 2; mt++)
        #pragma unroll
        for (int hf = 0; hf < 2; hf++) {
            int row = wm * 32 + mt * 16 + hf * 8 + g;
            float inv = 1.0f / (rred[row][4] + rred[row][5] +
                                rred[row][6] + rred[row][7]);
            #pragma unroll
            for (int nt = 0; nt < 8; nt++) {
                int c0 = wn * 64 + nt * 8 + t4 * 2;
                *(uint32_t*)(Cmat + (long long)(m0 + row) * 256 + c0) =
                    packbf(acc[mt][nt][hf * 2] * inv, acc[mt][nt][hf * 2 + 1] * inv);
            }
        }
}

// ---------------------------------------------------------------------------
// Small kernels
// ---------------------------------------------------------------------------
__global__ void f2b_kernel(const float4* __restrict__ in, uint2* __restrict__ out, int n4) {
    int i = blockIdx.x * 256 + threadIdx.x;
    if (i < n4) {
        float4 v = in[i];
        out[i] = make_uint2(packbf(v.x, v.y), packbf(v.z, v.w));
    }
}

__global__ void ln_kernel(const float* __restrict__ x, const float* __restrict__ w,
                          const float* __restrict__ bias, bf16* __restrict__ o) {
    __shared__ float sm[32];
    long long row = blockIdx.x;
    const float2* xr = (const float2*)(x + row * DIM);
    int t = threadIdx.x;
    float2 v = xr[t];
    float mu = bredSum(v.x + v.y, sm) * (1.0f / DIM);
    float d0 = v.x - mu, d1 = v.y - mu;
    float var = bredSum(d0 * d0 + d1 * d1, sm) * (1.0f / DIM);
    float rs = rsqrtf(var + 1e-5f);
    float2 wv = ((const float2*)w)[t];
    float2 bv = ((const float2*)bias)[t];
    ((uint32_t*)(o + row * DIM))[t] = packbf(d0 * rs * wv.x + bv.x, d1 * rs * wv.y + bv.y);
}

__global__ void vcopy_kernel(const bf16* __restrict__ qkv, bf16* __restrict__ vc) {
    long long idx = ((long long)blockIdx.x * 256 + threadIdx.x) * 8;
    long long d  = idx & 63;
    long long n  = (idx >> 6) & (N_TOK - 1);
    long long bh = idx >> 18;
    long long b = bh >> 3, h = bh & 7;
    uint4 v = *(const uint4*)(qkv + (b * N_TOK + n) * E3 + 2 * DIM + h * DH + d);
    *(uint4*)(vc + idx) = v;
}

__global__ void landmark_kernel(const bf16* __restrict__ qkv,
                                bf16* __restrict__ ql, bf16* __restrict__ kl) {
    int idx = blockIdx.x * 256 + threadIdx.x;
    int d  = idx & 63;
    int mi = (idx >> 6) & 255;
    int bh = idx >> 14;
    int bb = bh >> 3, h = bh & 7;
    const bf16* base = qkv + ((long long)(bb * N_TOK + mi * L_PER)) * E3 + h * DH + d;
    float sq = 0.f, sk = 0.f;
    #pragma unroll
    for (int j = 0; j < L_PER; j++) {
        sq += __bfloat162float(base[(long long)j * E3]);
        sk += __bfloat162float(base[(long long)j * E3 + DIM]);
    }
    ql[idx] = __float2bfloat16(sq * (0.125f / 16.0f));
    kl[idx] = __float2bfloat16(sk * (1.0f / 16.0f));
}

__global__ void reset_kernel(float* scal) {
    if (threadIdx.x < 2) scal[threadIdx.x] = 0.0f;
}

__global__ void pinv_reduce_kernel(const bf16* __restrict__ a2, float* __restrict__ scal) {
    int bh = blockIdx.x, j = threadIdx.x;
    const bf16* a = a2 + (long long)bh * (M_LM * M_LM);
    float cs = 0.f, rs = 0.f;
    for (int i = 0; i < M_LM; i++) {
        cs += fabsf(__bfloat162float(a[i * M_LM + j]));
        rs += fabsf(__bfloat162float(a[j * M_LM + i]));
    }
    atomicMax((int*)&scal[0], __float_as_int(rs));
    atomicMax((int*)&scal[1], __float_as_int(cs));
}

__global__ void zinit_kernel(const bf16* __restrict__ a2, bf16* __restrict__ z,
                             const float* __restrict__ scal) {
    float inv = 1.0f / (scal[0] * scal[1]);
    int idx = blockIdx.x * 256 + threadIdx.x;
    int bh = idx >> 16, r = (idx >> 8) & 255, c = idx & 255;
    z[idx] = __float2bfloat16(
        __bfloat162float(a2[((long long)bh << 16) + (c << 8) + r]) * inv);
}

#define CONV_TI 128
__global__ void __launch_bounds__(256)
conv_add_kernel(const bf16* __restrict__ vc, const float* __restrict__ cw,
                bf16* __restrict__ Y) {
    __shared__ float w[KER];
    __shared__ __align__(16) bf16 vs[(CONV_TI + 32) * 64];
    int bh = blockIdx.y;
    int bb = bh >> 3, h = bh & 7;
    int i0 = blockIdx.x * CONV_TI;
    int tid = threadIdx.x;
    if (tid < KER) w[tid] = cw[h * KER + tid];

    const bf16* vbase = vc + (long long)bh * N_TOK * DH;
    #pragma unroll
    for (int c = 0; c < 5; c++) {
        int chunk = tid + c * 256;
        int row = chunk >> 3, ch = chunk & 7;
        int r = i0 - 16 + row;
        uint4 val = make_uint4(0, 0, 0, 0);
        if (r >= 0 && r < N_TOK)
            val = *(const uint4*)(vbase + (long long)r * DH + ch * 8);
        *(uint4*)(&vs[row * 64 + ch * 8]) = val;
    }
    __syncthreads();

    int j = tid & 63, iy = tid >> 6;
    #pragma unroll
    for (int s = 0; s < CONV_TI / 4; s++) {
        int ii = iy + s * 4;
        float acc = 0.f;
        #pragma unroll
        for (int t = 0; t < KER; t++)
            acc += w[t] * __bfloat162float(vs[(ii + t) * 64 + j]);
        long long o = ((long long)(bb * N_TOK + i0 + ii)) * DIM + h * DH + j;
        Y[o] = __float2bfloat16(__bfloat162float(Y[o]) + acc);
    }
}

// ---------------------------------------------------------------------------
// Launcher
// ---------------------------------------------------------------------------
template <typename T, size_t N>
static T* symp(T (&s)[N]) {
    void* p = nullptr;
    cudaGetSymbolAddress(&p, s);
    return (T*)p;
}

extern "C" void kernel_launch(void* const* d_in, const int* in_sizes, int n_in,
                              void* d_out, int out_size) {
    const float* x      = (const float*)d_in[0];
    const float* ln_w   = (const float*)d_in[1];
    const float* ln_b   = (const float*)d_in[2];
    const float* qkv_w  = (const float*)d_in[3];
    const float* out_w  = (const float*)d_in[4];
    const float* out_b  = (const float*)d_in[5];
    const float* conv_w = (const float*)d_in[6];
    const float* omega  = (const float*)d_in[7];
    float* out = (float*)d_out;

    bf16* xn    = symp(g_xn);
    bf16* qkv   = symp(g_qkv);
    bf16* vc    = symp(g_vc);
    bf16* ql    = symp(g_ql);
    bf16* kl    = symp(g_kl);
    bf16* attn1 = symp(g_attn1);
    bf16* a2    = symp(g_a2);
    bf16* z     = symp(g_z);
    bf16* z2    = symp(g_z2);
    bf16* az    = symp(g_az);
    bf16* t1    = symp(g_t1);
    bf16* t2    = symp(g_t2);
    bf16* kv    = symp(g_kv);
    bf16* zkv   = symp(g_zkv);
    bf16* Y     = symp(g_y);
    bf16* qkvwb = symp(g_qkvw);
    bf16* outwb = symp(g_outw);
    float* scal = symp(g_scal);

    const long long sA1 = (long long)N_TOK * M_LM;
    const long long sLM = (long long)M_LM * DH;
    const long long sMM = (long long)M_LM * M_LM;
    const long long sQB = (long long)N_TOK * E3;

    // 0. Weight conversion
    f2b_kernel<<<(E3 * DIM / 4 + 255) / 256, 256>>>((const float4*)qkv_w, (uint2*)qkvwb,
                                                    E3 * DIM / 4);
    f2b_kernel<<<(DIM * DIM / 4 + 255) / 256, 256>>>((const float4*)out_w, (uint2*)outwb,
                                                     DIM * DIM / 4);

    // 1. LayerNorm
    ln_kernel<<<BN, 256>>>(x, ln_w, ln_b, xn);

    // 2. QKV projection
    launch_b128(true, xn, qkvwb, qkv, BN, E3, DIM, DIM, DIM, E3,
                0, 0, 0, 0, 0, 0, 1, 1, 1.0f, 0.0f);

    // 2b. v contiguous copy
    vcopy_kernel<<<(BHN * N_TOK * DH / 8) / 256, 256>>>(qkv, vc);

    // 3. Landmark means
    landmark_kernel<<<(BHN * M_LM * DH) / 256, 256>>>(qkv, ql, kl);

    // 4. attn1 = softmax(scale * q @ kl^T)
    {
        dim3 grid(1, N_TOK / 64, BHN);
        attn_sm_kernel<<<grid, 256>>>(qkv, kl, attn1, E3, DH,
            sQB, DH, 8 * sLM, sLM, 8 * sA1, sA1, 0.125f);
    }

    // 5. a2 = softmax(ql @ kl^T)
    {
        dim3 grid(1, M_LM / 64, BHN);
        attn_sm_kernel<<<grid, 256>>>(ql, kl, a2, DH, DH,
            8 * sLM, sLM, 8 * sLM, sLM, 8 * sMM, sMM, 1.0f);
    }

    // 6+8. kv = softmax(ql @ k^T) @ v   (flash-fused, no attn3 buffer)
    {
        dim3 grid(M_LM / 128, BHN);
        flash_kv_kernel<<<grid, 256>>>(ql, qkv, vc, kv);
    }

    // 7. pinv (6 Newton-Schulz iterations)
    reset_kernel<<<1, 32>>>(scal);
    pinv_reduce_kernel<<<BHN, 256>>>(a2, scal);
    zinit_kernel<<<(BHN * (int)sMM) / 256, 256>>>(a2, z, scal);

    bf16* zc = z;
    bf16* zn = z2;
    for (int it = 0; it < 6; it++) {
        {
            dim3 grid(M_LM / 128, M_LM / 128, BHN), block(256);
            bgemm_kernel<false, 32, 2><<<grid, block>>>(a2, zc, (void*)az, t1,
                nullptr, nullptr, nullptr, M_LM, M_LM, M_LM, M_LM,
                sMM, 0, sMM, 0, sMM, 0, 1, 1.0f, 7.0f);
        }
        launch_b128(false, az, t1, t2, M_LM, M_LM, M_LM, M_LM, M_LM, M_LM,
                    sMM, 0, sMM, 0, sMM, 0, 1, BHN, -1.0f, 15.0f);
        launch_b128(false, az, t2, t1, M_LM, M_LM, M_LM, M_LM, M_LM, M_LM,
                    sMM, 0, sMM, 0, sMM, 0, 1, BHN, -1.0f, 13.0f);
        launch_b128(false, zc, t1, zn, M_LM, M_LM, M_LM, M_LM, M_LM, M_LM,
                    sMM, 0, sMM, 0, sMM, 0, 1, BHN, 0.25f, 0.0f);
        bf16* tmp = zc; zc = zn; zn = tmp;
    }

    // 9. zkv = attn2_inv @ kv
    launch_b64(false, zc, kv, zkv, M_LM, DH, M_LM, M_LM, DH, DH,
               sMM, 0, sLM, 0, sLM, 0, 1, BHN, 1.0f, 0.0f);

    // 10. Y = attn1 @ zkv
    launch_b64(false, attn1, zkv, Y, N_TOK, DH, M_LM, M_LM, DH, DIM,
               8 * sA1, sA1, 8 * sLM, sLM, (long long)N_TOK * DIM, DH,
               HEADS, BHN, 1.0f, 0.0f);

    // 11. conv residual
    conv_add_kernel<<<dim3(N_TOK / CONV_TI, BHN), 256>>>(vc, conv_w, Y);

    // 12. out projection with fused admin residual
    {
        dim3 grid(DIM / 128, BN / 128, 1), block(256);
        bgemm_kernel<true, 32, 1><<<grid, block>>>(Y, outwb, (void*)out, nullptr,
            x, out_b, omega, DIM, DIM, DIM, DIM, 0, 0, 0, 0, 0, 0, 1, 1.0f, 0.0f);
    }
}